// round 2
// baseline (speedup 1.0000x reference)
#include <cuda_runtime.h>
#include <math.h>

// Problem constants
#define BB 8
#define NN_ 4096
#define MM_ 1024
#define DD 1024
#define HH 16
#define HDD 64
#define SCALE_F 0.125f
#define EPS_F 1e-6f

#define ROWS_X (BB * NN_)   // 32768
#define ROWS_W (BB * MM_)   // 8192

// ---------------------------------------------------------------------------
// Scratch buffers (static device globals; allocation at module load is legal)
// ---------------------------------------------------------------------------
__device__ float g_bufA[(size_t)ROWS_X * 4096];  // lnw (start), then FFN hidden h
__device__ float g_buf1[(size_t)ROWS_X * DD];    // ln1 -> attn_out -> ln2
__device__ float g_buf2[(size_t)ROWS_X * DD];    // q
__device__ float g_buf3[(size_t)ROWS_X * DD];    // x2
__device__ float g_kv[(size_t)ROWS_W * 2048];    // kv
__device__ float g_ctx[(size_t)BB * HH * HDD * HDD]; // per-head 64x64 context

// ---------------------------------------------------------------------------
// LayerNorm: one block (256 thr) per row of D=1024. Exact two-pass.
// ---------------------------------------------------------------------------
__global__ void ln_kernel(const float* __restrict__ x, const float* __restrict__ g,
                          const float* __restrict__ bta, float* __restrict__ y) {
    const int tid = threadIdx.x;
    const size_t row = blockIdx.x;
    const float4* xr = (const float4*)(x + row * DD);
    float4 v = xr[tid];
    __shared__ float red[32];

    float s = v.x + v.y + v.z + v.w;
    #pragma unroll
    for (int o = 16; o; o >>= 1) s += __shfl_xor_sync(0xffffffffu, s, o);
    if ((tid & 31) == 0) red[tid >> 5] = s;
    __syncthreads();
    if (tid < 32) {
        float t = (tid < 8) ? red[tid] : 0.f;
        #pragma unroll
        for (int o = 4; o; o >>= 1) t += __shfl_xor_sync(0xffffffffu, t, o);
        if (tid == 0) red[0] = t;
    }
    __syncthreads();
    const float mean = red[0] * (1.f / DD);

    float dx = v.x - mean, dy = v.y - mean, dz = v.z - mean, dw = v.w - mean;
    float ss = dx * dx + dy * dy + dz * dz + dw * dw;
    #pragma unroll
    for (int o = 16; o; o >>= 1) ss += __shfl_xor_sync(0xffffffffu, ss, o);
    __syncthreads();   // everyone has read red[0] before reuse
    if ((tid & 31) == 0) red[tid >> 5] = ss;
    __syncthreads();
    if (tid < 32) {
        float t = (tid < 8) ? red[tid] : 0.f;
        #pragma unroll
        for (int o = 4; o; o >>= 1) t += __shfl_xor_sync(0xffffffffu, t, o);
        if (tid == 0) red[0] = t;
    }
    __syncthreads();
    const float rstd = rsqrtf(red[0] * (1.f / DD) + EPS_F);

    float4 gg = ((const float4*)g)[tid];
    float4 bb = ((const float4*)bta)[tid];
    float4 o4;
    o4.x = dx * rstd * gg.x + bb.x;
    o4.y = dy * rstd * gg.y + bb.y;
    o4.z = dz * rstd * gg.z + bb.z;
    o4.w = dw * rstd * gg.w + bb.w;
    ((float4*)(y + row * DD))[tid] = o4;
}

// ---------------------------------------------------------------------------
// SGEMM: C[M,N] = A[M,K] @ B[K,N] + bias, with epilogue variants.
// 128x128x8 tiles, 256 threads, 8x8 per thread, double-buffered smem.
// EP: 0 = +bias ; 1 = +bias +res ; 2 = silu(+bias)
// ---------------------------------------------------------------------------
template <int EP>
__global__ void __launch_bounds__(256, 2)
sgemm(const float* __restrict__ A, const float* __restrict__ Bm,
      const float* __restrict__ bias, const float* __restrict__ res,
      float* __restrict__ C, int Mrows, int Ncols, int K) {
    __shared__ float As[2][8][128];
    __shared__ float Bs[2][8][128];
    const int tid = threadIdx.x;
    const int bm = blockIdx.y, bn = blockIdx.x;
    const int arow = tid >> 1, acol = (tid & 1) << 2;
    const int brow = tid >> 5, bcol = (tid & 31) << 2;
    const int tx = tid & 15, ty = tid >> 4;

    const float* Aptr = A + (size_t)(bm * 128 + arow) * K + acol;
    const float* Bptr = Bm + (size_t)brow * Ncols + bn * 128 + bcol;

    float acc[8][8];
    #pragma unroll
    for (int i = 0; i < 8; i++)
        #pragma unroll
        for (int j = 0; j < 8; j++) acc[i][j] = 0.f;

    {   // tile 0
        float4 a = *(const float4*)Aptr;
        As[0][acol + 0][arow] = a.x; As[0][acol + 1][arow] = a.y;
        As[0][acol + 2][arow] = a.z; As[0][acol + 3][arow] = a.w;
        *(float4*)&Bs[0][brow][bcol] = *(const float4*)Bptr;
    }
    __syncthreads();

    const int ntiles = K >> 3;
    for (int kt = 0; kt < ntiles; kt++) {
        const int cb = kt & 1;
        if (kt + 1 < ntiles) {
            const int nb = cb ^ 1;
            float4 a = *(const float4*)(Aptr + (kt + 1) * 8);
            As[nb][acol + 0][arow] = a.x; As[nb][acol + 1][arow] = a.y;
            As[nb][acol + 2][arow] = a.z; As[nb][acol + 3][arow] = a.w;
            *(float4*)&Bs[nb][brow][bcol] =
                *(const float4*)(Bptr + (size_t)(kt + 1) * 8 * Ncols);
        }
        #pragma unroll
        for (int k = 0; k < 8; k++) {
            float a[8], b[8];
            *(float4*)&a[0] = *(const float4*)&As[cb][k][ty * 8];
            *(float4*)&a[4] = *(const float4*)&As[cb][k][ty * 8 + 4];
            *(float4*)&b[0] = *(const float4*)&Bs[cb][k][tx * 8];
            *(float4*)&b[4] = *(const float4*)&Bs[cb][k][tx * 8 + 4];
            #pragma unroll
            for (int i = 0; i < 8; i++)
                #pragma unroll
                for (int j = 0; j < 8; j++) acc[i][j] += a[i] * b[j];
        }
        __syncthreads();
    }

    const int row0 = bm * 128 + ty * 8;
    const int col0 = bn * 128 + tx * 8;
    float bv[8];
    #pragma unroll
    for (int j = 0; j < 8; j++) bv[j] = bias[col0 + j];
    #pragma unroll
    for (int i = 0; i < 8; i++) {
        float* cp = C + (size_t)(row0 + i) * Ncols + col0;
        float o[8];
        #pragma unroll
        for (int j = 0; j < 8; j++) {
            float v = acc[i][j] + bv[j];
            if (EP == 1) v += res[(size_t)(row0 + i) * Ncols + col0 + j];
            if (EP == 2) v = v * (1.f / (1.f + __expf(-v)));
            o[j] = v;
        }
        *(float4*)cp       = *(float4*)&o[0];
        *(float4*)(cp + 4) = *(float4*)&o[4];
    }
}

// ---------------------------------------------------------------------------
// softmax over the N (sequence) axis of q[B,N,D], per (b, channel) column.
// grid = (D/32, B), block = (32, 8). Online (m,s) pass + write pass.
// ---------------------------------------------------------------------------
__global__ void softmax_q_kernel(float* __restrict__ q) {
    const int b = blockIdx.y;
    const int c = (blockIdx.x << 5) + threadIdx.x;
    const int ty = threadIdx.y;
    float* base = q + (size_t)b * NN_ * DD + c;

    float m = -1e30f, s = 0.f;
    for (int n = ty; n < NN_; n += 8) {
        float v = base[(size_t)n * DD];
        if (v > m) { s = s * __expf(m - v) + 1.f; m = v; }
        else       { s += __expf(v - m); }
    }
    __shared__ float sm[8][32], ssum[8][32];
    sm[ty][threadIdx.x] = m; ssum[ty][threadIdx.x] = s;
    __syncthreads();
    float Mv = -1e30f;
    #pragma unroll
    for (int i = 0; i < 8; i++) Mv = fmaxf(Mv, sm[i][threadIdx.x]);
    float Sv = 0.f;
    #pragma unroll
    for (int i = 0; i < 8; i++) Sv += ssum[i][threadIdx.x] * __expf(sm[i][threadIdx.x] - Mv);
    const float inv = 1.f / Sv;
    for (int n = ty; n < NN_; n += 8) {
        float v = base[(size_t)n * DD];
        base[(size_t)n * DD] = __expf(v - Mv) * inv;
    }
}

// ---------------------------------------------------------------------------
// softmax over each 64-wide head chunk of k = kv[:, :1024]. warp per chunk.
// grid = B*M rows, block = 512 (16 warps = 16 heads).
// ---------------------------------------------------------------------------
__global__ void softmax_k_kernel(float* __restrict__ kv) {
    const size_t row = blockIdx.x;
    const int w = threadIdx.x >> 5, lane = threadIdx.x & 31;
    float* p = kv + row * 2048 + w * 64;
    float a = p[lane], c = p[lane + 32];
    float m = fmaxf(a, c);
    #pragma unroll
    for (int o = 16; o; o >>= 1) m = fmaxf(m, __shfl_xor_sync(0xffffffffu, m, o));
    float ea = __expf(a - m), ec = __expf(c - m);
    float s = ea + ec;
    #pragma unroll
    for (int o = 16; o; o >>= 1) s += __shfl_xor_sync(0xffffffffu, s, o);
    const float inv = 1.f / s;
    p[lane] = ea * inv; p[lane + 32] = ec * inv;
}

// ---------------------------------------------------------------------------
// context[b,h,d,e] = SCALE * sum_m k[b,m,h*64+d] * v[b,m,h*64+e]
// grid = B*H blocks, 256 threads, each thread 4x4 of the 64x64 output.
// ---------------------------------------------------------------------------
__global__ void context_kernel(const float* __restrict__ kv, float* __restrict__ ctx) {
    const int bh = blockIdx.x;
    const int b = bh >> 4, h = bh & 15;
    __shared__ float Ks[64][64];
    __shared__ float Vs[64][64];
    const int tid = threadIdx.x;
    const int tx = tid & 15, ty = tid >> 4;
    const float* kvb = kv + (size_t)b * MM_ * 2048 + h * 64;

    float acc[4][4];
    #pragma unroll
    for (int i = 0; i < 4; i++)
        #pragma unroll
        for (int j = 0; j < 4; j++) acc[i][j] = 0.f;

    for (int m0 = 0; m0 < MM_; m0 += 64) {
        for (int i = tid; i < 1024; i += 256) {
            int r = i >> 4, c4 = (i & 15) << 2;
            const float* rp = kvb + (size_t)(m0 + r) * 2048 + c4;
            *(float4*)&Ks[r][c4] = *(const float4*)rp;
            *(float4*)&Vs[r][c4] = *(const float4*)(rp + 1024);
        }
        __syncthreads();
        #pragma unroll 8
        for (int mm = 0; mm < 64; mm++) {
            float a0 = Ks[mm][ty * 4 + 0], a1 = Ks[mm][ty * 4 + 1];
            float a2 = Ks[mm][ty * 4 + 2], a3 = Ks[mm][ty * 4 + 3];
            float b0 = Vs[mm][tx * 4 + 0], b1 = Vs[mm][tx * 4 + 1];
            float b2 = Vs[mm][tx * 4 + 2], b3 = Vs[mm][tx * 4 + 3];
            acc[0][0] += a0 * b0; acc[0][1] += a0 * b1; acc[0][2] += a0 * b2; acc[0][3] += a0 * b3;
            acc[1][0] += a1 * b0; acc[1][1] += a1 * b1; acc[1][2] += a1 * b2; acc[1][3] += a1 * b3;
            acc[2][0] += a2 * b0; acc[2][1] += a2 * b1; acc[2][2] += a2 * b2; acc[2][3] += a2 * b3;
            acc[3][0] += a3 * b0; acc[3][1] += a3 * b1; acc[3][2] += a3 * b2; acc[3][3] += a3 * b3;
        }
        __syncthreads();
    }
    float* cb = ctx + (size_t)bh * 64 * 64;
    #pragma unroll
    for (int i = 0; i < 4; i++) {
        float o[4];
        #pragma unroll
        for (int j = 0; j < 4; j++) o[j] = acc[i][j] * SCALE_F;
        *(float4*)(cb + (ty * 4 + i) * 64 + tx * 4) = *(float4*)&o[0];
    }
}

// ---------------------------------------------------------------------------
// out[b,n,h*64+e] = sum_d q[b,n,h*64+d] * ctx[b,h,d,e]
// grid = (N/64, B*H), 256 threads, each thread 4x4.
// ---------------------------------------------------------------------------
__global__ void apply_ctx_kernel(const float* __restrict__ q, const float* __restrict__ ctx,
                                 float* __restrict__ outp) {
    const int bh = blockIdx.y;
    const int b = bh >> 4, h = bh & 15;
    const int n0 = blockIdx.x << 6;
    __shared__ float Cs[64][64];
    __shared__ float Qs[64][64];
    const int tid = threadIdx.x;
    const float* qb = q + ((size_t)(b * NN_ + n0)) * DD + h * 64;
    const float* cb = ctx + (size_t)bh * 64 * 64;

    for (int i = tid; i < 1024; i += 256) {
        int r = i >> 4, c4 = (i & 15) << 2;
        *(float4*)&Cs[r][c4] = *(const float4*)(cb + r * 64 + c4);
        *(float4*)&Qs[r][c4] = *(const float4*)(qb + (size_t)r * DD + c4);
    }
    __syncthreads();

    const int tx = tid & 15, ty = tid >> 4;
    float acc[4][4];
    #pragma unroll
    for (int i = 0; i < 4; i++)
        #pragma unroll
        for (int j = 0; j < 4; j++) acc[i][j] = 0.f;

    #pragma unroll 8
    for (int d = 0; d < 64; d++) {
        float a0 = Qs[ty * 4 + 0][d], a1 = Qs[ty * 4 + 1][d];
        float a2 = Qs[ty * 4 + 2][d], a3 = Qs[ty * 4 + 3][d];
        float b0 = Cs[d][tx * 4 + 0], b1 = Cs[d][tx * 4 + 1];
        float b2 = Cs[d][tx * 4 + 2], b3 = Cs[d][tx * 4 + 3];
        acc[0][0] += a0 * b0; acc[0][1] += a0 * b1; acc[0][2] += a0 * b2; acc[0][3] += a0 * b3;
        acc[1][0] += a1 * b0; acc[1][1] += a1 * b1; acc[1][2] += a1 * b2; acc[1][3] += a1 * b3;
        acc[2][0] += a2 * b0; acc[2][1] += a2 * b1; acc[2][2] += a2 * b2; acc[2][3] += a2 * b3;
        acc[3][0] += a3 * b0; acc[3][1] += a3 * b1; acc[3][2] += a3 * b2; acc[3][3] += a3 * b3;
    }
    float* ob = outp + ((size_t)(b * NN_ + n0)) * DD + h * 64;
    #pragma unroll
    for (int i = 0; i < 4; i++)
        *(float4*)(ob + (size_t)(ty * 4 + i) * DD + tx * 4) = *(float4*)&acc[i][0];
}

// ---------------------------------------------------------------------------
// Launch sequence
// ---------------------------------------------------------------------------
extern "C" void kernel_launch(void* const* d_in, const int* in_sizes, int n_in,
                              void* d_out, int out_size) {
    (void)in_sizes; (void)n_in; (void)out_size;
    const float* x      = (const float*)d_in[0];
    const float* wt     = (const float*)d_in[1];
    const float* ln_q_g = (const float*)d_in[2];
    const float* ln_q_b = (const float*)d_in[3];
    const float* Wq     = (const float*)d_in[4];
    const float* bq     = (const float*)d_in[5];
    const float* ln_kv_g= (const float*)d_in[6];
    const float* ln_kv_b= (const float*)d_in[7];
    const float* Wkv    = (const float*)d_in[8];
    const float* bkv    = (const float*)d_in[9];
    const float* Wo     = (const float*)d_in[10];
    const float* bo     = (const float*)d_in[11];
    const float* ln_f_g = (const float*)d_in[12];
    const float* ln_f_b = (const float*)d_in[13];
    const float* W1     = (const float*)d_in[14];
    const float* b1     = (const float*)d_in[15];
    const float* W2     = (const float*)d_in[16];
    const float* b2     = (const float*)d_in[17];
    float* out = (float*)d_out;

    float *bufA, *buf1, *buf2, *buf3, *kv, *ctx;
    cudaGetSymbolAddress((void**)&bufA, g_bufA);
    cudaGetSymbolAddress((void**)&buf1, g_buf1);
    cudaGetSymbolAddress((void**)&buf2, g_buf2);
    cudaGetSymbolAddress((void**)&buf3, g_buf3);
    cudaGetSymbolAddress((void**)&kv,   g_kv);
    cudaGetSymbolAddress((void**)&ctx,  g_ctx);

    // 1. LN(x) -> buf1 ; LN(wavelet) -> bufA (front)
    ln_kernel<<<ROWS_X, 256>>>(x,  ln_q_g,  ln_q_b,  buf1);
    ln_kernel<<<ROWS_W, 256>>>(wt, ln_kv_g, ln_kv_b, bufA);

    // 2. q = buf1 @ Wq + bq -> buf2 ; kv = bufA @ Wkv + bkv -> kv
    sgemm<0><<<dim3(DD / 128, ROWS_X / 128), 256>>>(buf1, Wq, bq, nullptr, buf2,
                                                    ROWS_X, DD, DD);
    sgemm<0><<<dim3(2048 / 128, ROWS_W / 128), 256>>>(bufA, Wkv, bkv, nullptr, kv,
                                                      ROWS_W, 2048, DD);

    // 3. softmaxes
    softmax_q_kernel<<<dim3(DD / 32, BB), dim3(32, 8)>>>(buf2);
    softmax_k_kernel<<<ROWS_W, 512>>>(kv);

    // 4. context (SCALE folded) + apply ; attn -> buf1 (ln1 is dead)
    context_kernel<<<BB * HH, 256>>>(kv, ctx);
    apply_ctx_kernel<<<dim3(NN_ / 64, BB * HH), 256>>>(buf2, ctx, buf1);

    // 5. x2 = attn @ Wo + bo + x -> buf3
    sgemm<1><<<dim3(DD / 128, ROWS_X / 128), 256>>>(buf1, Wo, bo, x, buf3,
                                                    ROWS_X, DD, DD);

    // 6. LN(x2) -> buf1
    ln_kernel<<<ROWS_X, 256>>>(buf3, ln_f_g, ln_f_b, buf1);

    // 7. h = silu(buf1 @ W1 + b1) -> bufA
    sgemm<2><<<dim3(4096 / 128, ROWS_X / 128), 256>>>(buf1, W1, b1, nullptr, bufA,
                                                      ROWS_X, 4096, DD);

    // 8. out = bufA @ W2 + b2 + x2
    sgemm<1><<<dim3(DD / 128, ROWS_X / 128), 256>>>(bufA, W2, b2, buf3, out,
                                                    ROWS_X, DD, 4096);
}

// round 5
// speedup vs baseline: 3.1638x; 3.1638x over previous
#include <cuda_runtime.h>
#include <math.h>
#include <stdint.h>

// ---------------------------------------------------------------------------
// Problem constants
// ---------------------------------------------------------------------------
#define BB 8
#define NN_ 4096
#define MM_ 1024
#define DD 1024
#define HH 16
#define SCALE_F 0.125f
#define EPS_F 1e-6f
#define ROWS_X (BB * NN_)   // 32768
#define ROWS_W (BB * MM_)   // 8192

// ---------------------------------------------------------------------------
// Scratch (static device globals)
// ---------------------------------------------------------------------------
__device__ float g_bufA[(size_t)ROWS_X * 4096];  // lnw (front), then FFN hidden
__device__ float g_buf1[(size_t)ROWS_X * DD];    // ln1 -> attn_out -> ln2
__device__ float g_buf2[(size_t)ROWS_X * DD];    // q
__device__ float g_buf3[(size_t)ROWS_X * DD];    // x2
__device__ float g_kv[(size_t)ROWS_W * 2048];
__device__ float g_ctx[(size_t)BB * HH * 64 * 64];
// transposed (N,K) weights, tf32-rounded
__device__ float g_WqT[(size_t)1024 * 1024];
__device__ float g_WkvT[(size_t)2048 * 1024];
__device__ float g_WoT[(size_t)1024 * 1024];
__device__ float g_W1T[(size_t)4096 * 1024];
__device__ float g_W2T[(size_t)1024 * 4096];

// ---------------------------------------------------------------------------
// Helpers
// ---------------------------------------------------------------------------
__device__ __forceinline__ uint32_t smem_u32(const void* p) {
    uint32_t a;
    asm("{ .reg .u64 t; cvta.to.shared.u64 t, %1; cvt.u32.u64 %0, t; }"
        : "=r"(a) : "l"(p));
    return a;
}

// round-to-nearest tf32 (b32 destination register — required by PTX)
__device__ __forceinline__ float to_tf32(float x) {
    uint32_t u;
    asm("cvt.rna.tf32.f32 %0, %1;" : "=r"(u) : "f"(x));
    return __uint_as_float(u);
}

__device__ __forceinline__ void cp_async16(uint32_t smem, const void* gmem) {
    asm volatile("cp.async.cg.shared.global [%0], [%1], 16;\n"
                 :: "r"(smem), "l"(gmem));
}
#define CP_COMMIT() asm volatile("cp.async.commit_group;" ::: "memory")

__device__ __forceinline__ uint32_t lds32(uint32_t addr) {
    uint32_t v;
    asm volatile("ld.shared.b32 %0, [%1];" : "=r"(v) : "r"(addr));
    return v;
}

// m16n8k8 tf32 MMA (sm_80+, arch-portable)
__device__ __forceinline__ void mma_tf32(float* d, const uint32_t* a,
                                         const uint32_t* b) {
    asm volatile(
        "mma.sync.aligned.m16n8k8.row.col.f32.tf32.tf32.f32 "
        "{%0,%1,%2,%3}, {%4,%5,%6,%7}, {%8,%9}, {%0,%1,%2,%3};"
        : "+f"(d[0]), "+f"(d[1]), "+f"(d[2]), "+f"(d[3])
        : "r"(a[0]), "r"(a[1]), "r"(a[2]), "r"(a[3]), "r"(b[0]), "r"(b[1]));
}

// smem fragment address: tile rows of 32 floats (128 B), XOR swizzle on 16B units
__device__ __forceinline__ uint32_t fragoff(int r, int c) {
    return (uint32_t)(r * 128 + (((c >> 2) ^ (r & 7)) << 4) + ((c & 3) << 2));
}

// ---------------------------------------------------------------------------
// tf32 mma.sync GEMM: C[M,N] = A[M,K] @ BT[N,K]^T + bias (+res | silu)
// 128x128 CTA tile, 8 warps (4x2), warp tile 32x64, K-chunk=32,
// 3-stage cp.async pipeline with swizzled smem.
// EP: 0 = +bias ; 1 = +bias +res ; 2 = tf32round(silu(+bias))
// ---------------------------------------------------------------------------
#define STAGE_BYTES 32768          // A 16KB + B 16KB
#define NSTAGE 3
#define DSMEM_BYTES (NSTAGE * STAGE_BYTES)

template <int EP>
__global__ void __launch_bounds__(256)
tgemm(const float* __restrict__ A, const float* __restrict__ BT,
      const float* __restrict__ bias, const float* __restrict__ res,
      float* __restrict__ C, int Ncols, int K) {
    extern __shared__ char dsm[];
    const uint32_t smem0 = smem_u32(dsm);

    const int tid = threadIdx.x;
    const int lane = tid & 31, warp = tid >> 5;
    const int wy = warp >> 1, wx = warp & 1;        // 4x2 warp grid
    const int gid = lane >> 2, tig = lane & 3;      // mma fragment coords
    const int bm = blockIdx.y, bn = blockIdx.x;

    const float* Abase = A + (size_t)(bm * 128) * K;
    const float* Bbase = BT + (size_t)(bn * 128) * K;
    const int ntiles = K >> 5;

    float acc[2][8][4];
    #pragma unroll
    for (int mt = 0; mt < 2; mt++)
        #pragma unroll
        for (int nt = 0; nt < 8; nt++)
            #pragma unroll
            for (int r = 0; r < 4; r++) acc[mt][nt][r] = 0.f;

    // loader: 1024 16B units per operand, 256 threads x 4
    auto load_chunk = [&](int c) {
        const uint32_t so = smem0 + (c % NSTAGE) * STAGE_BYTES;
        const int k0 = c << 5;
        #pragma unroll
        for (int t = 0; t < 4; t++) {
            const int i = tid + t * 256;
            const int r = i >> 3, u = i & 7;
            const uint32_t du = (uint32_t)((u ^ (r & 7)) << 4);
            cp_async16(so + (uint32_t)(r * 128) + du,
                       Abase + (size_t)r * K + k0 + u * 4);
            cp_async16(so + 16384u + (uint32_t)(r * 128) + du,
                       Bbase + (size_t)r * K + k0 + u * 4);
        }
        CP_COMMIT();
    };

    load_chunk(0);
    load_chunk(1);

    for (int c = 0; c < ntiles; c++) {
        asm volatile("cp.async.wait_group 1;" ::: "memory");
        __syncthreads();

        // keep exactly 2 groups in flight (empty commit keeps the count honest)
        if (c + 2 < ntiles) load_chunk(c + 2);
        else CP_COMMIT();

        const uint32_t sA = smem0 + (c % NSTAGE) * STAGE_BYTES;
        const uint32_t sB = sA + 16384u;

        #pragma unroll
        for (int ks = 0; ks < 4; ks++) {
            const int kc = ks * 8 + tig;
            uint32_t a[2][4];
            #pragma unroll
            for (int mt = 0; mt < 2; mt++) {
                const int r0 = wy * 32 + mt * 16 + gid;
                a[mt][0] = lds32(sA + fragoff(r0,     kc));
                a[mt][1] = lds32(sA + fragoff(r0 + 8, kc));
                a[mt][2] = lds32(sA + fragoff(r0,     kc + 4));
                a[mt][3] = lds32(sA + fragoff(r0 + 8, kc + 4));
            }
            #pragma unroll
            for (int nt = 0; nt < 8; nt++) {
                const int n0 = wx * 64 + nt * 8 + gid;
                uint32_t b[2];
                b[0] = lds32(sB + fragoff(n0, kc));
                b[1] = lds32(sB + fragoff(n0, kc + 4));
                mma_tf32(acc[0][nt], a[0], b);
                mma_tf32(acc[1][nt], a[1], b);
            }
        }
        __syncthreads();
    }

    // epilogue: thread owns rows {r0, r0+8}, col pairs per n-tile
    #pragma unroll
    for (int mt = 0; mt < 2; mt++) {
        const int r0 = bm * 128 + wy * 32 + mt * 16 + gid;
        #pragma unroll
        for (int nt = 0; nt < 8; nt++) {
            const int col = bn * 128 + wx * 64 + nt * 8 + tig * 2;
            float2 b2 = *(const float2*)(bias + col);
            float v0 = acc[mt][nt][0] + b2.x;
            float v1 = acc[mt][nt][1] + b2.y;
            float v2 = acc[mt][nt][2] + b2.x;
            float v3 = acc[mt][nt][3] + b2.y;
            if (EP == 1) {
                float2 ra = *(const float2*)(res + (size_t)r0 * Ncols + col);
                float2 rb = *(const float2*)(res + (size_t)(r0 + 8) * Ncols + col);
                v0 += ra.x; v1 += ra.y; v2 += rb.x; v3 += rb.y;
            }
            if (EP == 2) {
                v0 = to_tf32(v0 * (1.f / (1.f + __expf(-v0))));
                v1 = to_tf32(v1 * (1.f / (1.f + __expf(-v1))));
                v2 = to_tf32(v2 * (1.f / (1.f + __expf(-v2))));
                v3 = to_tf32(v3 * (1.f / (1.f + __expf(-v3))));
            }
            *(float2*)(C + (size_t)r0 * Ncols + col)       = make_float2(v0, v1);
            *(float2*)(C + (size_t)(r0 + 8) * Ncols + col) = make_float2(v2, v3);
        }
    }
}

// ---------------------------------------------------------------------------
// Weight transpose: in[K][N] -> out[N][K], tf32-rounded output
// ---------------------------------------------------------------------------
__global__ void transpose_tf32(const float* __restrict__ in, float* __restrict__ out,
                               int K, int N) {
    __shared__ float t[32][33];
    const int bx = blockIdx.x * 32;  // n
    const int by = blockIdx.y * 32;  // k
    const int x = threadIdx.x, y = threadIdx.y;
    #pragma unroll
    for (int i = 0; i < 32; i += 8)
        t[y + i][x] = in[(size_t)(by + y + i) * N + bx + x];
    __syncthreads();
    #pragma unroll
    for (int i = 0; i < 32; i += 8)
        out[(size_t)(bx + y + i) * K + by + x] = to_tf32(t[x][y + i]);
}

// ---------------------------------------------------------------------------
// LayerNorm (tf32-rounded output: it only feeds GEMMs)
// ---------------------------------------------------------------------------
__global__ void ln_kernel(const float* __restrict__ x, const float* __restrict__ g,
                          const float* __restrict__ bta, float* __restrict__ y) {
    const int tid = threadIdx.x;
    const size_t row = blockIdx.x;
    float4 v = ((const float4*)(x + row * DD))[tid];
    __shared__ float red[32];

    float s = v.x + v.y + v.z + v.w;
    #pragma unroll
    for (int o = 16; o; o >>= 1) s += __shfl_xor_sync(0xffffffffu, s, o);
    if ((tid & 31) == 0) red[tid >> 5] = s;
    __syncthreads();
    if (tid < 32) {
        float t = (tid < 8) ? red[tid] : 0.f;
        #pragma unroll
        for (int o = 4; o; o >>= 1) t += __shfl_xor_sync(0xffffffffu, t, o);
        if (tid == 0) red[0] = t;
    }
    __syncthreads();
    const float mean = red[0] * (1.f / DD);

    float dx = v.x - mean, dy = v.y - mean, dz = v.z - mean, dw = v.w - mean;
    float ss = dx * dx + dy * dy + dz * dz + dw * dw;
    #pragma unroll
    for (int o = 16; o; o >>= 1) ss += __shfl_xor_sync(0xffffffffu, ss, o);
    __syncthreads();
    if ((tid & 31) == 0) red[tid >> 5] = ss;
    __syncthreads();
    if (tid < 32) {
        float t = (tid < 8) ? red[tid] : 0.f;
        #pragma unroll
        for (int o = 4; o; o >>= 1) t += __shfl_xor_sync(0xffffffffu, t, o);
        if (tid == 0) red[0] = t;
    }
    __syncthreads();
    const float rstd = rsqrtf(red[0] * (1.f / DD) + EPS_F);

    float4 gg = ((const float4*)g)[tid];
    float4 bb = ((const float4*)bta)[tid];
    float4 o4;
    o4.x = to_tf32(dx * rstd * gg.x + bb.x);
    o4.y = to_tf32(dy * rstd * gg.y + bb.y);
    o4.z = to_tf32(dz * rstd * gg.z + bb.z);
    o4.w = to_tf32(dw * rstd * gg.w + bb.w);
    ((float4*)(y + row * DD))[tid] = o4;
}

// ---------------------------------------------------------------------------
// softmax over N axis of q[B,N,D] per (b, channel)
// ---------------------------------------------------------------------------
__global__ void softmax_q_kernel(float* __restrict__ q) {
    const int b = blockIdx.y;
    const int c = (blockIdx.x << 5) + threadIdx.x;
    const int ty = threadIdx.y;
    float* base = q + (size_t)b * NN_ * DD + c;

    float m = -1e30f, s = 0.f;
    for (int n = ty; n < NN_; n += 8) {
        float v = base[(size_t)n * DD];
        if (v > m) { s = s * __expf(m - v) + 1.f; m = v; }
        else       { s += __expf(v - m); }
    }
    __shared__ float sm[8][32], ssum[8][32];
    sm[ty][threadIdx.x] = m; ssum[ty][threadIdx.x] = s;
    __syncthreads();
    float Mv = -1e30f;
    #pragma unroll
    for (int i = 0; i < 8; i++) Mv = fmaxf(Mv, sm[i][threadIdx.x]);
    float Sv = 0.f;
    #pragma unroll
    for (int i = 0; i < 8; i++) Sv += ssum[i][threadIdx.x] * __expf(sm[i][threadIdx.x] - Mv);
    const float inv = 1.f / Sv;
    for (int n = ty; n < NN_; n += 8) {
        float v = base[(size_t)n * DD];
        base[(size_t)n * DD] = __expf(v - Mv) * inv;
    }
}

// softmax over each 64-wide head chunk of k
__global__ void softmax_k_kernel(float* __restrict__ kv) {
    const size_t row = blockIdx.x;
    const int w = threadIdx.x >> 5, lane = threadIdx.x & 31;
    float* p = kv + row * 2048 + w * 64;
    float a = p[lane], c = p[lane + 32];
    float m = fmaxf(a, c);
    #pragma unroll
    for (int o = 16; o; o >>= 1) m = fmaxf(m, __shfl_xor_sync(0xffffffffu, m, o));
    float ea = __expf(a - m), ec = __expf(c - m);
    float s = ea + ec;
    #pragma unroll
    for (int o = 16; o; o >>= 1) s += __shfl_xor_sync(0xffffffffu, s, o);
    const float inv = 1.f / s;
    p[lane] = ea * inv; p[lane + 32] = ec * inv;
}

// context[b,h,:,:] = SCALE * k^T v  (64x64 per head)
__global__ void context_kernel(const float* __restrict__ kv, float* __restrict__ ctx) {
    const int bh = blockIdx.x;
    const int b = bh >> 4, h = bh & 15;
    __shared__ float Ks[64][64];
    __shared__ float Vs[64][64];
    const int tid = threadIdx.x;
    const int tx = tid & 15, ty = tid >> 4;
    const float* kvb = kv + (size_t)b * MM_ * 2048 + h * 64;

    float acc[4][4];
    #pragma unroll
    for (int i = 0; i < 4; i++)
        #pragma unroll
        for (int j = 0; j < 4; j++) acc[i][j] = 0.f;

    for (int m0 = 0; m0 < MM_; m0 += 64) {
        for (int i = tid; i < 1024; i += 256) {
            int r = i >> 4, c4 = (i & 15) << 2;
            const float* rp = kvb + (size_t)(m0 + r) * 2048 + c4;
            *(float4*)&Ks[r][c4] = *(const float4*)rp;
            *(float4*)&Vs[r][c4] = *(const float4*)(rp + 1024);
        }
        __syncthreads();
        #pragma unroll 8
        for (int mm = 0; mm < 64; mm++) {
            float a0 = Ks[mm][ty * 4 + 0], a1 = Ks[mm][ty * 4 + 1];
            float a2 = Ks[mm][ty * 4 + 2], a3 = Ks[mm][ty * 4 + 3];
            float b0 = Vs[mm][tx * 4 + 0], b1 = Vs[mm][tx * 4 + 1];
            float b2 = Vs[mm][tx * 4 + 2], b3 = Vs[mm][tx * 4 + 3];
            acc[0][0] += a0 * b0; acc[0][1] += a0 * b1; acc[0][2] += a0 * b2; acc[0][3] += a0 * b3;
            acc[1][0] += a1 * b0; acc[1][1] += a1 * b1; acc[1][2] += a1 * b2; acc[1][3] += a1 * b3;
            acc[2][0] += a2 * b0; acc[2][1] += a2 * b1; acc[2][2] += a2 * b2; acc[2][3] += a2 * b3;
            acc[3][0] += a3 * b0; acc[3][1] += a3 * b1; acc[3][2] += a3 * b2; acc[3][3] += a3 * b3;
        }
        __syncthreads();
    }
    float* cb = ctx + (size_t)bh * 64 * 64;
    #pragma unroll
    for (int i = 0; i < 4; i++) {
        float o[4];
        #pragma unroll
        for (int j = 0; j < 4; j++) o[j] = acc[i][j] * SCALE_F;
        *(float4*)(cb + (ty * 4 + i) * 64 + tx * 4) = *(float4*)&o[0];
    }
}

// out[b,n,h*64+e] = sum_d q[b,n,h*64+d] * ctx[b,h,d,e]  (tf32-rounded: feeds Wo GEMM)
__global__ void apply_ctx_kernel(const float* __restrict__ q, const float* __restrict__ ctx,
                                 float* __restrict__ outp) {
    const int bh = blockIdx.y;
    const int b = bh >> 4, h = bh & 15;
    const int n0 = blockIdx.x << 6;
    __shared__ float Cs[64][64];
    __shared__ float Qs[64][64];
    const int tid = threadIdx.x;
    const float* qb = q + ((size_t)(b * NN_ + n0)) * DD + h * 64;
    const float* cb = ctx + (size_t)bh * 64 * 64;

    for (int i = tid; i < 1024; i += 256) {
        int r = i >> 4, c4 = (i & 15) << 2;
        *(float4*)&Cs[r][c4] = *(const float4*)(cb + r * 64 + c4);
        *(float4*)&Qs[r][c4] = *(const float4*)(qb + (size_t)r * DD + c4);
    }
    __syncthreads();

    const int tx = tid & 15, ty = tid >> 4;
    float acc[4][4];
    #pragma unroll
    for (int i = 0; i < 4; i++)
        #pragma unroll
        for (int j = 0; j < 4; j++) acc[i][j] = 0.f;

    #pragma unroll 8
    for (int d = 0; d < 64; d++) {
        float a0 = Qs[ty * 4 + 0][d], a1 = Qs[ty * 4 + 1][d];
        float a2 = Qs[ty * 4 + 2][d], a3 = Qs[ty * 4 + 3][d];
        float b0 = Cs[d][tx * 4 + 0], b1 = Cs[d][tx * 4 + 1];
        float b2 = Cs[d][tx * 4 + 2], b3 = Cs[d][tx * 4 + 3];
        acc[0][0] += a0 * b0; acc[0][1] += a0 * b1; acc[0][2] += a0 * b2; acc[0][3] += a0 * b3;
        acc[1][0] += a1 * b0; acc[1][1] += a1 * b1; acc[1][2] += a1 * b2; acc[1][3] += a1 * b3;
        acc[2][0] += a2 * b0; acc[2][1] += a2 * b1; acc[2][2] += a2 * b2; acc[2][3] += a2 * b3;
        acc[3][0] += a3 * b0; acc[3][1] += a3 * b1; acc[3][2] += a3 * b2; acc[3][3] += a3 * b3;
    }
    float* ob = outp + ((size_t)(b * NN_ + n0)) * DD + h * 64;
    #pragma unroll
    for (int i = 0; i < 4; i++) {
        float o[4];
        #pragma unroll
        for (int j = 0; j < 4; j++) o[j] = to_tf32(acc[i][j]);
        *(float4*)(ob + (size_t)(ty * 4 + i) * DD + tx * 4) = *(float4*)&o[0];
    }
}

// ---------------------------------------------------------------------------
// Launch sequence
// ---------------------------------------------------------------------------
extern "C" void kernel_launch(void* const* d_in, const int* in_sizes, int n_in,
                              void* d_out, int out_size) {
    (void)in_sizes; (void)n_in; (void)out_size;
    const float* x      = (const float*)d_in[0];
    const float* wt     = (const float*)d_in[1];
    const float* ln_q_g = (const float*)d_in[2];
    const float* ln_q_b = (const float*)d_in[3];
    const float* Wq     = (const float*)d_in[4];
    const float* bq     = (const float*)d_in[5];
    const float* ln_kv_g= (const float*)d_in[6];
    const float* ln_kv_b= (const float*)d_in[7];
    const float* Wkv    = (const float*)d_in[8];
    const float* bkv    = (const float*)d_in[9];
    const float* Wo     = (const float*)d_in[10];
    const float* bo     = (const float*)d_in[11];
    const float* ln_f_g = (const float*)d_in[12];
    const float* ln_f_b = (const float*)d_in[13];
    const float* W1     = (const float*)d_in[14];
    const float* b1     = (const float*)d_in[15];
    const float* W2     = (const float*)d_in[16];
    const float* b2     = (const float*)d_in[17];
    float* out = (float*)d_out;

    float *bufA, *buf1, *buf2, *buf3, *kv, *ctx;
    float *WqT, *WkvT, *WoT, *W1T, *W2T;
    cudaGetSymbolAddress((void**)&bufA, g_bufA);
    cudaGetSymbolAddress((void**)&buf1, g_buf1);
    cudaGetSymbolAddress((void**)&buf2, g_buf2);
    cudaGetSymbolAddress((void**)&buf3, g_buf3);
    cudaGetSymbolAddress((void**)&kv,   g_kv);
    cudaGetSymbolAddress((void**)&ctx,  g_ctx);
    cudaGetSymbolAddress((void**)&WqT,  g_WqT);
    cudaGetSymbolAddress((void**)&WkvT, g_WkvT);
    cudaGetSymbolAddress((void**)&WoT,  g_WoT);
    cudaGetSymbolAddress((void**)&W1T,  g_W1T);
    cudaGetSymbolAddress((void**)&W2T,  g_W2T);

    cudaFuncSetAttribute(tgemm<0>, cudaFuncAttributeMaxDynamicSharedMemorySize, DSMEM_BYTES);
    cudaFuncSetAttribute(tgemm<1>, cudaFuncAttributeMaxDynamicSharedMemorySize, DSMEM_BYTES);
    cudaFuncSetAttribute(tgemm<2>, cudaFuncAttributeMaxDynamicSharedMemorySize, DSMEM_BYTES);

    // 0. transpose + tf32-round weights
    transpose_tf32<<<dim3(1024 / 32, 1024 / 32), dim3(32, 8)>>>(Wq,  WqT,  1024, 1024);
    transpose_tf32<<<dim3(2048 / 32, 1024 / 32), dim3(32, 8)>>>(Wkv, WkvT, 1024, 2048);
    transpose_tf32<<<dim3(1024 / 32, 1024 / 32), dim3(32, 8)>>>(Wo,  WoT,  1024, 1024);
    transpose_tf32<<<dim3(4096 / 32, 1024 / 32), dim3(32, 8)>>>(W1,  W1T,  1024, 4096);
    transpose_tf32<<<dim3(1024 / 32, 4096 / 32), dim3(32, 8)>>>(W2,  W2T,  4096, 1024);

    // 1. LN
    ln_kernel<<<ROWS_X, 256>>>(x,  ln_q_g,  ln_q_b,  buf1);
    ln_kernel<<<ROWS_W, 256>>>(wt, ln_kv_g, ln_kv_b, bufA);

    // 2. q / kv projections (tf32 mma.sync)
    tgemm<0><<<dim3(DD / 128, ROWS_X / 128), 256, DSMEM_BYTES>>>(buf1, WqT, bq, nullptr,
                                                                 buf2, DD, DD);
    tgemm<0><<<dim3(2048 / 128, ROWS_W / 128), 256, DSMEM_BYTES>>>(bufA, WkvT, bkv, nullptr,
                                                                   kv, 2048, DD);

    // 3. softmaxes + linear attention core
    softmax_q_kernel<<<dim3(DD / 32, BB), dim3(32, 8)>>>(buf2);
    softmax_k_kernel<<<ROWS_W, 512>>>(kv);
    context_kernel<<<BB * HH, 256>>>(kv, ctx);
    apply_ctx_kernel<<<dim3(NN_ / 64, BB * HH), 256>>>(buf2, ctx, buf1);

    // 4. x2 = attn @ Wo + bo + x
    tgemm<1><<<dim3(DD / 128, ROWS_X / 128), 256, DSMEM_BYTES>>>(buf1, WoT, bo, x,
                                                                 buf3, DD, DD);

    // 5. LN(x2)
    ln_kernel<<<ROWS_X, 256>>>(buf3, ln_f_g, ln_f_b, buf1);

    // 6. h = silu(ln2 @ W1 + b1)
    tgemm<2><<<dim3(4096 / 128, ROWS_X / 128), 256, DSMEM_BYTES>>>(buf1, W1T, b1, nullptr,
                                                                   bufA, 4096, DD);

    // 7. out = h @ W2 + b2 + x2
    tgemm<1><<<dim3(DD / 128, ROWS_X / 128), 256, DSMEM_BYTES>>>(bufA, W2T, b2, buf3,
                                                                 out, DD, 4096);
}

// round 6
// speedup vs baseline: 3.4222x; 1.0817x over previous
#include <cuda_runtime.h>
#include <math.h>
#include <stdint.h>

// ---------------------------------------------------------------------------
// Problem constants
// ---------------------------------------------------------------------------
#define BB 8
#define NN_ 4096
#define MM_ 1024
#define DD 1024
#define HH 16
#define SCALE_F 0.125f
#define EPS_F 1e-6f
#define ROWS_X (BB * NN_)   // 32768
#define ROWS_W (BB * MM_)   // 8192

// ---------------------------------------------------------------------------
// Scratch (static device globals)
// ---------------------------------------------------------------------------
__device__ float g_bufA[(size_t)ROWS_X * 4096];  // lnw (front), then FFN hidden
__device__ float g_buf1[(size_t)ROWS_X * DD];    // ln1 -> attn_out -> ln2
__device__ float g_buf2[(size_t)ROWS_X * DD];    // q
__device__ float g_buf3[(size_t)ROWS_X * DD];    // x2
__device__ float g_kv[(size_t)ROWS_W * 2048];
__device__ float g_ctx[(size_t)BB * HH * 64 * 64];
// transposed (N,K) weights, tf32-rounded
__device__ float g_WqT[(size_t)1024 * 1024];
__device__ float g_WkvT[(size_t)2048 * 1024];
__device__ float g_WoT[(size_t)1024 * 1024];
__device__ float g_W1T[(size_t)4096 * 1024];
__device__ float g_W2T[(size_t)1024 * 4096];

// ---------------------------------------------------------------------------
// Helpers
// ---------------------------------------------------------------------------
__device__ __forceinline__ uint32_t smem_u32(const void* p) {
    uint32_t a;
    asm("{ .reg .u64 t; cvta.to.shared.u64 t, %1; cvt.u32.u64 %0, t; }"
        : "=r"(a) : "l"(p));
    return a;
}

// round-to-nearest tf32 (b32 destination register — required by PTX)
__device__ __forceinline__ float to_tf32(float x) {
    uint32_t u;
    asm("cvt.rna.tf32.f32 %0, %1;" : "=r"(u) : "f"(x));
    return __uint_as_float(u);
}

__device__ __forceinline__ void cp_async16(uint32_t smem, const void* gmem) {
    asm volatile("cp.async.cg.shared.global [%0], [%1], 16;\n"
                 :: "r"(smem), "l"(gmem));
}
#define CP_COMMIT() asm volatile("cp.async.commit_group;" ::: "memory")

__device__ __forceinline__ uint32_t lds32(uint32_t addr) {
    uint32_t v;
    asm volatile("ld.shared.b32 %0, [%1];" : "=r"(v) : "r"(addr));
    return v;
}

// m16n8k8 tf32 MMA (sm_80+, arch-portable)
__device__ __forceinline__ void mma_tf32(float* d, const uint32_t* a,
                                         const uint32_t* b) {
    asm volatile(
        "mma.sync.aligned.m16n8k8.row.col.f32.tf32.tf32.f32 "
        "{%0,%1,%2,%3}, {%4,%5,%6,%7}, {%8,%9}, {%0,%1,%2,%3};"
        : "+f"(d[0]), "+f"(d[1]), "+f"(d[2]), "+f"(d[3])
        : "r"(a[0]), "r"(a[1]), "r"(a[2]), "r"(a[3]), "r"(b[0]), "r"(b[1]));
}

// smem fragment address: tile rows of 32 floats (128 B), XOR swizzle on 16B units
__device__ __forceinline__ uint32_t fragoff(int r, int c) {
    return (uint32_t)(r * 128 + (((c >> 2) ^ (r & 7)) << 4) + ((c & 3) << 2));
}

// ---------------------------------------------------------------------------
// tf32 mma.sync GEMM: C[M,N] = A[M,K] @ BT[N,K]^T + bias (+res | silu)
// CTA tile 256x128, 8 warps (4x2), warp tile 64x64, K-chunk=32,
// 3-stage cp.async pipeline with swizzled smem (48KB/stage).
// EP: 0 = +bias ; 1 = +bias +res ; 2 = tf32round(silu(+bias))
// ---------------------------------------------------------------------------
#define A_STAGE_BYTES 32768u       // 256 rows x 32 k x 4B
#define B_STAGE_BYTES 16384u       // 128 rows x 32 k x 4B
#define STAGE_BYTES (A_STAGE_BYTES + B_STAGE_BYTES)
#define NSTAGE 3
#define DSMEM_BYTES (NSTAGE * STAGE_BYTES)

template <int EP>
__global__ void __launch_bounds__(256)
tgemm(const float* __restrict__ A, const float* __restrict__ BT,
      const float* __restrict__ bias, const float* __restrict__ res,
      float* __restrict__ C, int Ncols, int K) {
    extern __shared__ char dsm[];
    const uint32_t smem0 = smem_u32(dsm);

    const int tid = threadIdx.x;
    const int lane = tid & 31, warp = tid >> 5;
    const int wy = warp >> 1, wx = warp & 1;        // 4x2 warp grid
    const int gid = lane >> 2, tig = lane & 3;      // mma fragment coords
    const int bm = blockIdx.y, bn = blockIdx.x;

    const float* Abase = A + (size_t)(bm * 256) * K;
    const float* Bbase = BT + (size_t)(bn * 128) * K;
    const int ntiles = K >> 5;

    float acc[4][8][4];
    #pragma unroll
    for (int mt = 0; mt < 4; mt++)
        #pragma unroll
        for (int nt = 0; nt < 8; nt++)
            #pragma unroll
            for (int r = 0; r < 4; r++) acc[mt][nt][r] = 0.f;

    // loader: A = 2048 16B units (256 thr x 8), B = 1024 (256 thr x 4)
    auto load_chunk = [&](int c) {
        const uint32_t so = smem0 + (uint32_t)(c % NSTAGE) * STAGE_BYTES;
        const int k0 = c << 5;
        #pragma unroll
        for (int t = 0; t < 8; t++) {
            const int i = tid + t * 256;
            const int r = i >> 3, u = i & 7;
            const uint32_t du = (uint32_t)((u ^ (r & 7)) << 4);
            cp_async16(so + (uint32_t)(r * 128) + du,
                       Abase + (size_t)r * K + k0 + u * 4);
        }
        #pragma unroll
        for (int t = 0; t < 4; t++) {
            const int i = tid + t * 256;
            const int r = i >> 3, u = i & 7;
            const uint32_t du = (uint32_t)((u ^ (r & 7)) << 4);
            cp_async16(so + A_STAGE_BYTES + (uint32_t)(r * 128) + du,
                       Bbase + (size_t)r * K + k0 + u * 4);
        }
        CP_COMMIT();
    };

    load_chunk(0);
    load_chunk(1);

    for (int c = 0; c < ntiles; c++) {
        asm volatile("cp.async.wait_group 1;" ::: "memory");
        __syncthreads();

        // keep exactly 2 groups in flight (empty commit keeps the count honest)
        if (c + 2 < ntiles) load_chunk(c + 2);
        else CP_COMMIT();

        const uint32_t sA = smem0 + (uint32_t)(c % NSTAGE) * STAGE_BYTES;
        const uint32_t sB = sA + A_STAGE_BYTES;

        #pragma unroll
        for (int ks = 0; ks < 4; ks++) {
            const int kc = ks * 8 + tig;
            uint32_t a[4][4];
            #pragma unroll
            for (int mt = 0; mt < 4; mt++) {
                const int r0 = wy * 64 + mt * 16 + gid;
                a[mt][0] = lds32(sA + fragoff(r0,     kc));
                a[mt][1] = lds32(sA + fragoff(r0 + 8, kc));
                a[mt][2] = lds32(sA + fragoff(r0,     kc + 4));
                a[mt][3] = lds32(sA + fragoff(r0 + 8, kc + 4));
            }
            #pragma unroll
            for (int nt = 0; nt < 8; nt++) {
                const int n0 = wx * 64 + nt * 8 + gid;
                uint32_t b[2];
                b[0] = lds32(sB + fragoff(n0, kc));
                b[1] = lds32(sB + fragoff(n0, kc + 4));
                #pragma unroll
                for (int mt = 0; mt < 4; mt++)
                    mma_tf32(acc[mt][nt], a[mt], b);
            }
        }
        __syncthreads();
    }

    // epilogue: thread owns rows {r0, r0+8}, col pairs per n-tile
    #pragma unroll
    for (int mt = 0; mt < 4; mt++) {
        const int r0 = bm * 256 + wy * 64 + mt * 16 + gid;
        #pragma unroll
        for (int nt = 0; nt < 8; nt++) {
            const int col = bn * 128 + wx * 64 + nt * 8 + tig * 2;
            float2 b2 = *(const float2*)(bias + col);
            float v0 = acc[mt][nt][0] + b2.x;
            float v1 = acc[mt][nt][1] + b2.y;
            float v2 = acc[mt][nt][2] + b2.x;
            float v3 = acc[mt][nt][3] + b2.y;
            if (EP == 1) {
                float2 ra = *(const float2*)(res + (size_t)r0 * Ncols + col);
                float2 rb = *(const float2*)(res + (size_t)(r0 + 8) * Ncols + col);
                v0 += ra.x; v1 += ra.y; v2 += rb.x; v3 += rb.y;
            }
            if (EP == 2) {
                v0 = to_tf32(v0 * (1.f / (1.f + __expf(-v0))));
                v1 = to_tf32(v1 * (1.f / (1.f + __expf(-v1))));
                v2 = to_tf32(v2 * (1.f / (1.f + __expf(-v2))));
                v3 = to_tf32(v3 * (1.f / (1.f + __expf(-v3))));
            }
            *(float2*)(C + (size_t)r0 * Ncols + col)       = make_float2(v0, v1);
            *(float2*)(C + (size_t)(r0 + 8) * Ncols + col) = make_float2(v2, v3);
        }
    }
}

// ---------------------------------------------------------------------------
// Weight transpose: in[K][N] -> out[N][K], tf32-rounded output
// ---------------------------------------------------------------------------
__global__ void transpose_tf32(const float* __restrict__ in, float* __restrict__ out,
                               int K, int N) {
    __shared__ float t[32][33];
    const int bx = blockIdx.x * 32;  // n
    const int by = blockIdx.y * 32;  // k
    const int x = threadIdx.x, y = threadIdx.y;
    #pragma unroll
    for (int i = 0; i < 32; i += 8)
        t[y + i][x] = in[(size_t)(by + y + i) * N + bx + x];
    __syncthreads();
    #pragma unroll
    for (int i = 0; i < 32; i += 8)
        out[(size_t)(bx + y + i) * K + by + x] = to_tf32(t[x][y + i]);
}

// ---------------------------------------------------------------------------
// LayerNorm (tf32-rounded output: it only feeds GEMMs)
// ---------------------------------------------------------------------------
__global__ void ln_kernel(const float* __restrict__ x, const float* __restrict__ g,
                          const float* __restrict__ bta, float* __restrict__ y) {
    const int tid = threadIdx.x;
    const size_t row = blockIdx.x;
    float4 v = ((const float4*)(x + row * DD))[tid];
    __shared__ float red[32];

    float s = v.x + v.y + v.z + v.w;
    #pragma unroll
    for (int o = 16; o; o >>= 1) s += __shfl_xor_sync(0xffffffffu, s, o);
    if ((tid & 31) == 0) red[tid >> 5] = s;
    __syncthreads();
    if (tid < 32) {
        float t = (tid < 8) ? red[tid] : 0.f;
        #pragma unroll
        for (int o = 4; o; o >>= 1) t += __shfl_xor_sync(0xffffffffu, t, o);
        if (tid == 0) red[0] = t;
    }
    __syncthreads();
    const float mean = red[0] * (1.f / DD);

    float dx = v.x - mean, dy = v.y - mean, dz = v.z - mean, dw = v.w - mean;
    float ss = dx * dx + dy * dy + dz * dz + dw * dw;
    #pragma unroll
    for (int o = 16; o; o >>= 1) ss += __shfl_xor_sync(0xffffffffu, ss, o);
    __syncthreads();
    if ((tid & 31) == 0) red[tid >> 5] = ss;
    __syncthreads();
    if (tid < 32) {
        float t = (tid < 8) ? red[tid] : 0.f;
        #pragma unroll
        for (int o = 4; o; o >>= 1) t += __shfl_xor_sync(0xffffffffu, t, o);
        if (tid == 0) red[0] = t;
    }
    __syncthreads();
    const float rstd = rsqrtf(red[0] * (1.f / DD) + EPS_F);

    float4 gg = ((const float4*)g)[tid];
    float4 bb = ((const float4*)bta)[tid];
    float4 o4;
    o4.x = to_tf32(dx * rstd * gg.x + bb.x);
    o4.y = to_tf32(dy * rstd * gg.y + bb.y);
    o4.z = to_tf32(dz * rstd * gg.z + bb.z);
    o4.w = to_tf32(dw * rstd * gg.w + bb.w);
    ((float4*)(y + row * DD))[tid] = o4;
}

// ---------------------------------------------------------------------------
// softmax over N axis of q[B,N,D] per (b, channel)
// ---------------------------------------------------------------------------
__global__ void softmax_q_kernel(float* __restrict__ q) {
    const int b = blockIdx.y;
    const int c = (blockIdx.x << 5) + threadIdx.x;
    const int ty = threadIdx.y;
    float* base = q + (size_t)b * NN_ * DD + c;

    float m = -1e30f, s = 0.f;
    for (int n = ty; n < NN_; n += 8) {
        float v = base[(size_t)n * DD];
        if (v > m) { s = s * __expf(m - v) + 1.f; m = v; }
        else       { s += __expf(v - m); }
    }
    __shared__ float sm[8][32], ssum[8][32];
    sm[ty][threadIdx.x] = m; ssum[ty][threadIdx.x] = s;
    __syncthreads();
    float Mv = -1e30f;
    #pragma unroll
    for (int i = 0; i < 8; i++) Mv = fmaxf(Mv, sm[i][threadIdx.x]);
    float Sv = 0.f;
    #pragma unroll
    for (int i = 0; i < 8; i++) Sv += ssum[i][threadIdx.x] * __expf(sm[i][threadIdx.x] - Mv);
    const float inv = 1.f / Sv;
    for (int n = ty; n < NN_; n += 8) {
        float v = base[(size_t)n * DD];
        base[(size_t)n * DD] = __expf(v - Mv) * inv;
    }
}

// softmax over each 64-wide head chunk of k
__global__ void softmax_k_kernel(float* __restrict__ kv) {
    const size_t row = blockIdx.x;
    const int w = threadIdx.x >> 5, lane = threadIdx.x & 31;
    float* p = kv + row * 2048 + w * 64;
    float a = p[lane], c = p[lane + 32];
    float m = fmaxf(a, c);
    #pragma unroll
    for (int o = 16; o; o >>= 1) m = fmaxf(m, __shfl_xor_sync(0xffffffffu, m, o));
    float ea = __expf(a - m), ec = __expf(c - m);
    float s = ea + ec;
    #pragma unroll
    for (int o = 16; o; o >>= 1) s += __shfl_xor_sync(0xffffffffu, s, o);
    const float inv = 1.f / s;
    p[lane] = ea * inv; p[lane + 32] = ec * inv;
}

// context[b,h,:,:] = SCALE * k^T v  (64x64 per head)
__global__ void context_kernel(const float* __restrict__ kv, float* __restrict__ ctx) {
    const int bh = blockIdx.x;
    const int b = bh >> 4, h = bh & 15;
    __shared__ float Ks[64][64];
    __shared__ float Vs[64][64];
    const int tid = threadIdx.x;
    const int tx = tid & 15, ty = tid >> 4;
    const float* kvb = kv + (size_t)b * MM_ * 2048 + h * 64;

    float acc[4][4];
    #pragma unroll
    for (int i = 0; i < 4; i++)
        #pragma unroll
        for (int j = 0; j < 4; j++) acc[i][j] = 0.f;

    for (int m0 = 0; m0 < MM_; m0 += 64) {
        for (int i = tid; i < 1024; i += 256) {
            int r = i >> 4, c4 = (i & 15) << 2;
            const float* rp = kvb + (size_t)(m0 + r) * 2048 + c4;
            *(float4*)&Ks[r][c4] = *(const float4*)rp;
            *(float4*)&Vs[r][c4] = *(const float4*)(rp + 1024);
        }
        __syncthreads();
        #pragma unroll 8
        for (int mm = 0; mm < 64; mm++) {
            float a0 = Ks[mm][ty * 4 + 0], a1 = Ks[mm][ty * 4 + 1];
            float a2 = Ks[mm][ty * 4 + 2], a3 = Ks[mm][ty * 4 + 3];
            float b0 = Vs[mm][tx * 4 + 0], b1 = Vs[mm][tx * 4 + 1];
            float b2 = Vs[mm][tx * 4 + 2], b3 = Vs[mm][tx * 4 + 3];
            acc[0][0] += a0 * b0; acc[0][1] += a0 * b1; acc[0][2] += a0 * b2; acc[0][3] += a0 * b3;
            acc[1][0] += a1 * b0; acc[1][1] += a1 * b1; acc[1][2] += a1 * b2; acc[1][3] += a1 * b3;
            acc[2][0] += a2 * b0; acc[2][1] += a2 * b1; acc[2][2] += a2 * b2; acc[2][3] += a2 * b3;
            acc[3][0] += a3 * b0; acc[3][1] += a3 * b1; acc[3][2] += a3 * b2; acc[3][3] += a3 * b3;
        }
        __syncthreads();
    }
    float* cb = ctx + (size_t)bh * 64 * 64;
    #pragma unroll
    for (int i = 0; i < 4; i++) {
        float o[4];
        #pragma unroll
        for (int j = 0; j < 4; j++) o[j] = acc[i][j] * SCALE_F;
        *(float4*)(cb + (ty * 4 + i) * 64 + tx * 4) = *(float4*)&o[0];
    }
}

// out[b,n,h*64+e] = sum_d q[b,n,h*64+d] * ctx[b,h,d,e]  (tf32-rounded: feeds Wo GEMM)
__global__ void apply_ctx_kernel(const float* __restrict__ q, const float* __restrict__ ctx,
                                 float* __restrict__ outp) {
    const int bh = blockIdx.y;
    const int b = bh >> 4, h = bh & 15;
    const int n0 = blockIdx.x << 6;
    __shared__ float Cs[64][64];
    __shared__ float Qs[64][64];
    const int tid = threadIdx.x;
    const float* qb = q + ((size_t)(b * NN_ + n0)) * DD + h * 64;
    const float* cb = ctx + (size_t)bh * 64 * 64;

    for (int i = tid; i < 1024; i += 256) {
        int r = i >> 4, c4 = (i & 15) << 2;
        *(float4*)&Cs[r][c4] = *(const float4*)(cb + r * 64 + c4);
        *(float4*)&Qs[r][c4] = *(const float4*)(qb + (size_t)r * DD + c4);
    }
    __syncthreads();

    const int tx = tid & 15, ty = tid >> 4;
    float acc[4][4];
    #pragma unroll
    for (int i = 0; i < 4; i++)
        #pragma unroll
        for (int j = 0; j < 4; j++) acc[i][j] = 0.f;

    #pragma unroll 8
    for (int d = 0; d < 64; d++) {
        float a0 = Qs[ty * 4 + 0][d], a1 = Qs[ty * 4 + 1][d];
        float a2 = Qs[ty * 4 + 2][d], a3 = Qs[ty * 4 + 3][d];
        float b0 = Cs[d][tx * 4 + 0], b1 = Cs[d][tx * 4 + 1];
        float b2 = Cs[d][tx * 4 + 2], b3 = Cs[d][tx * 4 + 3];
        acc[0][0] += a0 * b0; acc[0][1] += a0 * b1; acc[0][2] += a0 * b2; acc[0][3] += a0 * b3;
        acc[1][0] += a1 * b0; acc[1][1] += a1 * b1; acc[1][2] += a1 * b2; acc[1][3] += a1 * b3;
        acc[2][0] += a2 * b0; acc[2][1] += a2 * b1; acc[2][2] += a2 * b2; acc[2][3] += a2 * b3;
        acc[3][0] += a3 * b0; acc[3][1] += a3 * b1; acc[3][2] += a3 * b2; acc[3][3] += a3 * b3;
    }
    float* ob = outp + ((size_t)(b * NN_ + n0)) * DD + h * 64;
    #pragma unroll
    for (int i = 0; i < 4; i++) {
        float o[4];
        #pragma unroll
        for (int j = 0; j < 4; j++) o[j] = to_tf32(acc[i][j]);
        *(float4*)(ob + (size_t)(ty * 4 + i) * DD + tx * 4) = *(float4*)&o[0];
    }
}

// ---------------------------------------------------------------------------
// Launch sequence
// ---------------------------------------------------------------------------
extern "C" void kernel_launch(void* const* d_in, const int* in_sizes, int n_in,
                              void* d_out, int out_size) {
    (void)in_sizes; (void)n_in; (void)out_size;
    const float* x      = (const float*)d_in[0];
    const float* wt     = (const float*)d_in[1];
    const float* ln_q_g = (const float*)d_in[2];
    const float* ln_q_b = (const float*)d_in[3];
    const float* Wq     = (const float*)d_in[4];
    const float* bq     = (const float*)d_in[5];
    const float* ln_kv_g= (const float*)d_in[6];
    const float* ln_kv_b= (const float*)d_in[7];
    const float* Wkv    = (const float*)d_in[8];
    const float* bkv    = (const float*)d_in[9];
    const float* Wo     = (const float*)d_in[10];
    const float* bo     = (const float*)d_in[11];
    const float* ln_f_g = (const float*)d_in[12];
    const float* ln_f_b = (const float*)d_in[13];
    const float* W1     = (const float*)d_in[14];
    const float* b1     = (const float*)d_in[15];
    const float* W2     = (const float*)d_in[16];
    const float* b2     = (const float*)d_in[17];
    float* out = (float*)d_out;

    float *bufA, *buf1, *buf2, *buf3, *kv, *ctx;
    float *WqT, *WkvT, *WoT, *W1T, *W2T;
    cudaGetSymbolAddress((void**)&bufA, g_bufA);
    cudaGetSymbolAddress((void**)&buf1, g_buf1);
    cudaGetSymbolAddress((void**)&buf2, g_buf2);
    cudaGetSymbolAddress((void**)&buf3, g_buf3);
    cudaGetSymbolAddress((void**)&kv,   g_kv);
    cudaGetSymbolAddress((void**)&ctx,  g_ctx);
    cudaGetSymbolAddress((void**)&WqT,  g_WqT);
    cudaGetSymbolAddress((void**)&WkvT, g_WkvT);
    cudaGetSymbolAddress((void**)&WoT,  g_WoT);
    cudaGetSymbolAddress((void**)&W1T,  g_W1T);
    cudaGetSymbolAddress((void**)&W2T,  g_W2T);

    cudaFuncSetAttribute(tgemm<0>, cudaFuncAttributeMaxDynamicSharedMemorySize, DSMEM_BYTES);
    cudaFuncSetAttribute(tgemm<1>, cudaFuncAttributeMaxDynamicSharedMemorySize, DSMEM_BYTES);
    cudaFuncSetAttribute(tgemm<2>, cudaFuncAttributeMaxDynamicSharedMemorySize, DSMEM_BYTES);

    // 0. transpose + tf32-round weights
    transpose_tf32<<<dim3(1024 / 32, 1024 / 32), dim3(32, 8)>>>(Wq,  WqT,  1024, 1024);
    transpose_tf32<<<dim3(2048 / 32, 1024 / 32), dim3(32, 8)>>>(Wkv, WkvT, 1024, 2048);
    transpose_tf32<<<dim3(1024 / 32, 1024 / 32), dim3(32, 8)>>>(Wo,  WoT,  1024, 1024);
    transpose_tf32<<<dim3(4096 / 32, 1024 / 32), dim3(32, 8)>>>(W1,  W1T,  1024, 4096);
    transpose_tf32<<<dim3(1024 / 32, 4096 / 32), dim3(32, 8)>>>(W2,  W2T,  4096, 1024);

    // 1. LN
    ln_kernel<<<ROWS_X, 256>>>(x,  ln_q_g,  ln_q_b,  buf1);
    ln_kernel<<<ROWS_W, 256>>>(wt, ln_kv_g, ln_kv_b, bufA);

    // 2. q / kv projections (tf32 mma.sync, 256x128 tiles)
    tgemm<0><<<dim3(DD / 128, ROWS_X / 256), 256, DSMEM_BYTES>>>(buf1, WqT, bq, nullptr,
                                                                 buf2, DD, DD);
    tgemm<0><<<dim3(2048 / 128, ROWS_W / 256), 256, DSMEM_BYTES>>>(bufA, WkvT, bkv, nullptr,
                                                                   kv, 2048, DD);

    // 3. softmaxes + linear attention core
    softmax_q_kernel<<<dim3(DD / 32, BB), dim3(32, 8)>>>(buf2);
    softmax_k_kernel<<<ROWS_W, 512>>>(kv);
    context_kernel<<<BB * HH, 256>>>(kv, ctx);
    apply_ctx_kernel<<<dim3(NN_ / 64, BB * HH), 256>>>(buf2, ctx, buf1);

    // 4. x2 = attn @ Wo + bo + x
    tgemm<1><<<dim3(DD / 128, ROWS_X / 256), 256, DSMEM_BYTES>>>(buf1, WoT, bo, x,
                                                                 buf3, DD, DD);

    // 5. LN(x2)
    ln_kernel<<<ROWS_X, 256>>>(buf3, ln_f_g, ln_f_b, buf1);

    // 6. h = silu(ln2 @ W1 + b1)
    tgemm<2><<<dim3(4096 / 128, ROWS_X / 256), 256, DSMEM_BYTES>>>(buf1, W1T, b1, nullptr,
                                                                   bufA, 4096, DD);

    // 7. out = h @ W2 + b2 + x2
    tgemm<1><<<dim3(DD / 128, ROWS_X / 256), 256, DSMEM_BYTES>>>(bufA, W2T, b2, buf3,
                                                                 out, DD, 4096);
}